// round 3
// baseline (speedup 1.0000x reference)
#include <cuda_runtime.h>
#include <math.h>

#define BW   128          // cells (threads) per block
#define SPAN (BW + 2)     // staged span length in faces/verts (+halo)

__device__ double       g_part[8192];
__device__ unsigned int g_cnt = 0;

struct V3 { float x, y, z; };

__device__ __forceinline__ V3 ld3(const float* p) { return {p[0], p[1], p[2]}; }
__device__ __forceinline__ V3 vsub(V3 a, V3 b) { return {a.x - b.x, a.y - b.y, a.z - b.z}; }
__device__ __forceinline__ float vdot(V3 a, V3 b) { return a.x * b.x + a.y * b.y + a.z * b.z; }
__device__ __forceinline__ V3 vcross(V3 a, V3 b) {
    return {a.y * b.z - a.z * b.y,
            a.z * b.x - a.x * b.z,
            a.x * b.y - a.y * b.x};
}
__device__ __forceinline__ V3 face_normal(const float* q) {
    V3 t0 = ld3(q), t1 = ld3(q + 3), t2 = ld3(q + 6);
    V3 c = vcross(vsub(t0, t1), vsub(t0, t2));
    float s = rsqrtf(vdot(c, c));
    return {c.x * s, c.y * s, c.z * s};
}
__device__ __forceinline__ float tri_area(V3 p1, V3 p2, V3 p3) {
    V3 c = vcross(vsub(p2, p1), vsub(p3, p1));
    return 0.5f * sqrtf(vdot(c, c));
}

// Closed form of (pair*coeff).sum()/9 with x = na@(r1-r2), y = nb@(r1-r2).
__device__ __forceinline__ double edge_term(
    V3 u, V3 w, V3 na, V3 nb,
    const float* r1, const float* r2,
    float dv2, float asum)
{
    float dr[9];
    #pragma unroll
    for (int i = 0; i < 9; i++) dr[i] = r1[i] - r2[i];

    V3 x = {na.x * dr[0] + na.y * dr[3] + na.z * dr[6],
            na.x * dr[1] + na.y * dr[4] + na.z * dr[7],
            na.x * dr[2] + na.y * dr[5] + na.z * dr[8]};
    V3 y = {nb.x * dr[0] + nb.y * dr[3] + nb.z * dr[6],
            nb.x * dr[1] + nb.y * dr[4] + nb.z * dr[7],
            nb.x * dr[2] + nb.y * dr[5] + nb.z * dr[8]};

    float en = (3.0f * (vdot(u, u) + vdot(w, w) + vdot(u, w))
              + vdot(x, x) + vdot(y, y) + vdot(x, y)) * (1.0f / 9.0f);
    return (double)(en * (dv2 / asum));
}

// Coalesced span copy (4B elements), clamped against [0, limFloats).
__device__ __forceinline__ void copy_span(float* dst, const float* __restrict__ src,
                                          int startFloat, int nFloats, int limFloats, int tid)
{
    for (int k = tid; k < nFloats; k += BW) {
        int g = startFloat + k;
        if (g >= limFloats) g = limFloats - 1;
        dst[k] = src[g];
    }
}

// One thread per grid cell (i, j). Each cell owns up to 3 edges:
//   diagonal   (v10,v01): tri1(i,j)  vs tri2(i,j)
//   horizontal (v10,v11): tri2(i,j)  vs tri1(i+1,j)   [i < m-1]
//   vertical   (v11,v01): tri2(i,j)  vs tri1(i,j+1)   [j < m-1]
// tri1(i,j) = i*m+j, tri2(i,j) = m*m + i*m+j.  Edge-endpoint "normals" are
// tp[vertex_id] blocks (reference indexes normals by vertex ids).
__global__ __launch_bounds__(BW)
void k_cell(const float* __restrict__ tp,     // (F,3,3)
            const float* __restrict__ rot,    // (F,3,3)
            const float* __restrict__ verts,  // (V,3)
            float* __restrict__ out,
            int n, int nblocks)
{
    const int m   = n - 1;
    const int i   = blockIdx.y;
    const int j0  = blockIdx.x * BW;
    const int tid = threadIdx.x;

    __shared__ float sT1[SPAN * 9], sT2[SPAN * 9], sTD[SPAN * 9];
    __shared__ float sNA[SPAN * 9], sNB[SPAN * 9];
    __shared__ float sR1[SPAN * 9], sR2[SPAN * 9], sRD[SPAN * 9];
    __shared__ float sV0[SPAN * 3], sV1[SPAN * 3], sV2[SPAN * 3];
    __shared__ double sred[4];
    __shared__ int s_last;

    const int limTP = 2 * m * m * 9;     // floats in tp / rot
    const int limV  = n * n * 3;         // floats in verts

    // ---- stage all spans with coalesced loads ----
    copy_span(sT1, tp,  (i * m + j0) * 9,               SPAN * 9, limTP, tid);
    copy_span(sT2, tp,  (m * m + i * m + j0) * 9,       SPAN * 9, limTP, tid);
    copy_span(sTD, tp,  ((i + 1) * m + j0) * 9,         SPAN * 9, limTP, tid);
    copy_span(sNA, tp,  ((i + 1) * n + j0) * 9,         SPAN * 9, limTP, tid);
    copy_span(sNB, tp,  (i * n + j0 + 1) * 9,           SPAN * 9, limTP, tid);
    copy_span(sR1, rot, (i * m + j0) * 9,               SPAN * 9, limTP, tid);
    copy_span(sR2, rot, (m * m + i * m + j0) * 9,       SPAN * 9, limTP, tid);
    copy_span(sRD, rot, ((i + 1) * m + j0) * 9,         SPAN * 9, limTP, tid);
    copy_span(sV0, verts, (i * n + j0) * 3,             SPAN * 3, limV, tid);
    copy_span(sV1, verts, ((i + 1) * n + j0) * 3,       SPAN * 3, limV, tid);
    copy_span(sV2, verts, ((i + 2) * n + j0) * 3,       SPAN * 3, limV, tid);
    __syncthreads();

    // ---- per-cell compute ----
    const int j = j0 + tid;
    double val = 0.0;

    if (j < m) {
        const int k = tid;

        V3 p00 = ld3(sV0 + 3 * k);
        V3 p01 = ld3(sV0 + 3 * (k + 1));
        V3 p02 = ld3(sV0 + 3 * (k + 2));
        V3 p10 = ld3(sV1 + 3 * k);
        V3 p11 = ld3(sV1 + 3 * (k + 1));
        V3 p20 = ld3(sV2 + 3 * k);

        float aT1 = tri_area(p00, p10, p01);
        float aT2 = tri_area(p10, p11, p01);

        const float* q1 = sT1 + 9 * k;
        const float* q2 = sT2 + 9 * k;
        V3 t1_1 = ld3(q1 + 3), t1_2 = ld3(q1 + 6);
        V3 t2_0 = ld3(q2),     t2_1 = ld3(q2 + 3), t2_2 = ld3(q2 + 6);

        V3 n10 = face_normal(sNA + 9 * k);         // tp[v10]
        V3 n11 = face_normal(sNA + 9 * (k + 1));   // tp[v11]
        V3 n01 = face_normal(sNB + 9 * k);         // tp[v01]

        const float* r1 = sR1 + 9 * k;
        const float* r2 = sR2 + 9 * k;

        // diagonal edge (v10, v01)
        {
            V3 u = vsub(t1_1, t2_0);
            V3 w = vsub(t1_2, t2_2);
            V3 d = vsub(p10, p01);
            val += edge_term(u, w, n10, n01, r1, r2, vdot(d, d), aT1 + aT2);
        }
        // horizontal edge (v10, v11) vs tri1(i+1, j)
        if (i < m - 1) {
            const float* qd = sTD + 9 * k;
            V3 td_0 = ld3(qd), td_2 = ld3(qd + 6);
            float aD = tri_area(p10, p20, p11);
            V3 u = vsub(t2_0, td_0);
            V3 w = vsub(t2_1, td_2);
            V3 d = vsub(p10, p11);
            val += edge_term(u, w, n10, n11, r2, sRD + 9 * k, vdot(d, d), aT2 + aD);
        }
        // vertical edge (v11, v01) vs tri1(i, j+1)
        if (j < m - 1) {
            const float* qr = sT1 + 9 * (k + 1);
            V3 tr_0 = ld3(qr), tr_1 = ld3(qr + 3);
            float aR = tri_area(p01, p11, p02);
            V3 u = vsub(t2_1, tr_1);
            V3 w = vsub(t2_2, tr_0);
            V3 d = vsub(p11, p01);
            val += edge_term(u, w, n11, n01, r2, sR1 + 9 * (k + 1), vdot(d, d), aT2 + aR);
        }
    }

    // ---- block reduction (4 warps) ----
    #pragma unroll
    for (int off = 16; off > 0; off >>= 1)
        val += __shfl_down_sync(0xFFFFFFFFu, val, off);
    int lane = tid & 31, wid = tid >> 5;
    if (lane == 0) sred[wid] = val;
    __syncthreads();

    const int bid = blockIdx.y * gridDim.x + blockIdx.x;
    if (tid == 0) {
        double bsum = sred[0] + sred[1] + sred[2] + sred[3];
        g_part[bid] = bsum;
        __threadfence();
        unsigned old = atomicAdd(&g_cnt, 1u);
        s_last = (old == (unsigned)(nblocks - 1)) ? 1 : 0;
    }
    __syncthreads();

    // ---- last block finalizes: reduce all partials, write out, reset counter ----
    if (s_last) {
        double v = 0.0;
        for (int p = tid; p < nblocks; p += BW)
            v += g_part[p];
        #pragma unroll
        for (int off = 16; off > 0; off >>= 1)
            v += __shfl_down_sync(0xFFFFFFFFu, v, off);
        if (lane == 0) sred[wid] = v;
        __syncthreads();
        if (tid == 0) {
            out[0] = (float)(sred[0] + sred[1] + sred[2] + sred[3]);
            g_cnt = 0;   // self-reset -> graph-replay safe
        }
    }
}

extern "C" void kernel_launch(void* const* d_in, const int* in_sizes, int n_in,
                              void* d_out, int out_size)
{
    const float* tp    = (const float*)d_in[0];   // (F,3,3)
    const float* rot   = (const float*)d_in[1];   // (F,3,3)
    const float* verts = (const float*)d_in[2];   // (1,V,3)

    int V = in_sizes[2] / 3;
    int n = (int)(sqrt((double)V) + 0.5);
    int m = n - 1;

    dim3 block(BW, 1, 1);
    dim3 grid((m + BW - 1) / BW, m, 1);
    int nblocks = grid.x * grid.y;

    k_cell<<<grid, block>>>(tp, rot, verts, (float*)d_out, n, nblocks);
}

// round 4
// speedup vs baseline: 5.2990x; 5.2990x over previous
#include <cuda_runtime.h>
#include <math.h>

__device__ double       g_sum = 0.0;
__device__ unsigned int g_cnt = 0;

struct V3 { float x, y, z; };

__device__ __forceinline__ V3 ld3(const float* __restrict__ p) { return {p[0], p[1], p[2]}; }
__device__ __forceinline__ V3 vsub(V3 a, V3 b) { return {a.x - b.x, a.y - b.y, a.z - b.z}; }
__device__ __forceinline__ float vdot(V3 a, V3 b) { return a.x * b.x + a.y * b.y + a.z * b.z; }
__device__ __forceinline__ V3 vcross(V3 a, V3 b) {
    return {a.y * b.z - a.z * b.y,
            a.z * b.x - a.x * b.z,
            a.x * b.y - a.y * b.x};
}
__device__ __forceinline__ V3 face_normal(const float* __restrict__ q) {
    V3 t0 = ld3(q), t1 = ld3(q + 3), t2 = ld3(q + 6);
    V3 c = vcross(vsub(t0, t1), vsub(t0, t2));
    float s = rsqrtf(vdot(c, c));
    return {c.x * s, c.y * s, c.z * s};
}
__device__ __forceinline__ float tri_area(V3 p1, V3 p2, V3 p3) {
    V3 c = vcross(vsub(p2, p1), vsub(p3, p1));
    return 0.5f * sqrtf(vdot(c, c));
}

// Closed form of (pair*coeff).sum()/9 with x = na@(r1-r2), y = nb@(r1-r2).
__device__ __forceinline__ double edge_term(
    V3 u, V3 w, V3 na, V3 nb,
    const float* __restrict__ r1, const float* __restrict__ r2,
    float dv2, float asum)
{
    float dr[9];
    #pragma unroll
    for (int i = 0; i < 9; i++) dr[i] = r1[i] - r2[i];

    V3 x = {na.x * dr[0] + na.y * dr[3] + na.z * dr[6],
            na.x * dr[1] + na.y * dr[4] + na.z * dr[7],
            na.x * dr[2] + na.y * dr[5] + na.z * dr[8]};
    V3 y = {nb.x * dr[0] + nb.y * dr[3] + nb.z * dr[6],
            nb.x * dr[1] + nb.y * dr[4] + nb.z * dr[7],
            nb.x * dr[2] + nb.y * dr[5] + nb.z * dr[8]};

    float en = (3.0f * (vdot(u, u) + vdot(w, w) + vdot(u, w))
              + vdot(x, x) + vdot(y, y) + vdot(x, y)) * (1.0f / 9.0f);
    return (double)(en * (dv2 / asum));
}

// One thread per grid cell (i, j). Each cell owns up to 3 interior edges:
//   diagonal   (v10,v01): tri1(i,j)  vs tri2(i,j)
//   horizontal (v10,v11): tri2(i,j)  vs tri1(i+1,j)   [i < m-1]
//   vertical   (v11,v01): tri2(i,j)  vs tri1(i,j+1)   [j < m-1]
// tri1(i,j) = i*m+j, tri2(i,j) = m*m + i*m+j (m = n-1).  Edge-endpoint
// "normals" come from tp[vertex_id] (reference indexes normals by vertex ids).
__global__ __launch_bounds__(256)
void k_cell(const float* __restrict__ tp,     // (F,3,3)
            const float* __restrict__ rot,    // (F,3,3)
            const float* __restrict__ verts,  // (V,3)
            float* __restrict__ out,
            int n, int nblocks)
{
    const int m = n - 1;
    int j = blockIdx.x * blockDim.x + threadIdx.x;
    int i = blockIdx.y;
    double val = 0.0;

    if (j < m) {
        int v00 = i * n + j;
        int v10 = v00 + n;
        int v01 = v00 + 1;
        int v11 = v10 + 1;

        int fT1 = i * m + j;
        int fT2 = m * m + fT1;

        V3 p00 = ld3(verts + 3 * (size_t)v00);
        V3 p10 = ld3(verts + 3 * (size_t)v10);
        V3 p01 = ld3(verts + 3 * (size_t)v01);
        V3 p11 = ld3(verts + 3 * (size_t)v11);

        float aT1 = tri_area(p00, p10, p01);
        float aT2 = tri_area(p10, p11, p01);

        const float* q1 = tp + 9 * (size_t)fT1;
        const float* q2 = tp + 9 * (size_t)fT2;
        V3 t1_1 = ld3(q1 + 3), t1_2 = ld3(q1 + 6);
        V3 t2_0 = ld3(q2),     t2_1 = ld3(q2 + 3), t2_2 = ld3(q2 + 6);

        V3 n10 = face_normal(tp + 9 * (size_t)v10);
        V3 n01 = face_normal(tp + 9 * (size_t)v01);
        V3 n11 = face_normal(tp + 9 * (size_t)v11);

        const float* r1 = rot + 9 * (size_t)fT1;
        const float* r2 = rot + 9 * (size_t)fT2;

        // diagonal edge (v10, v01)
        {
            V3 u = vsub(t1_1, t2_0);
            V3 w = vsub(t1_2, t2_2);
            V3 d = vsub(p10, p01);
            val += edge_term(u, w, n10, n01, r1, r2, vdot(d, d), aT1 + aT2);
        }
        // horizontal edge (v10, v11) vs tri1(i+1, j)
        if (i < m - 1) {
            int fD = fT1 + m;
            const float* qd = tp + 9 * (size_t)fD;
            V3 td_0 = ld3(qd), td_2 = ld3(qd + 6);
            V3 p20 = ld3(verts + 3 * (size_t)(v10 + n));
            float aD = tri_area(p10, p20, p11);
            V3 u = vsub(t2_0, td_0);
            V3 w = vsub(t2_1, td_2);
            V3 d = vsub(p10, p11);
            val += edge_term(u, w, n10, n11, r2, rot + 9 * (size_t)fD, vdot(d, d), aT2 + aD);
        }
        // vertical edge (v11, v01) vs tri1(i, j+1)
        if (j < m - 1) {
            int fR = fT1 + 1;
            const float* qr = tp + 9 * (size_t)fR;
            V3 tr_0 = ld3(qr), tr_1 = ld3(qr + 3);
            V3 p02 = ld3(verts + 3 * (size_t)(v01 + 1));
            float aR = tri_area(p01, p11, p02);
            V3 u = vsub(t2_1, tr_1);
            V3 w = vsub(t2_2, tr_0);
            V3 d = vsub(p11, p01);
            val += edge_term(u, w, n11, n01, r2, rot + 9 * (size_t)fR, vdot(d, d), aT2 + aR);
        }
    }

    // ---- block reduction in double ----
    #pragma unroll
    for (int off = 16; off > 0; off >>= 1)
        val += __shfl_down_sync(0xFFFFFFFFu, val, off);

    __shared__ double sh[8];
    __shared__ int s_last;
    int lane = threadIdx.x & 31;
    int wid  = threadIdx.x >> 5;
    if (lane == 0) sh[wid] = val;
    __syncthreads();

    if (threadIdx.x == 0) {
        double bsum = 0.0;
        #pragma unroll
        for (int w = 0; w < 8; w++) bsum += sh[w];
        atomicAdd(&g_sum, bsum);
        __threadfence();
        unsigned old = atomicAdd(&g_cnt, 1u);
        s_last = (old == (unsigned)(nblocks - 1)) ? 1 : 0;
    }
    __syncthreads();

    // ---- last block writes output and resets accumulators (graph-replay safe) ----
    if (s_last && threadIdx.x == 0) {
        out[0] = (float)g_sum;
        g_sum = 0.0;
        g_cnt = 0;
    }
}

extern "C" void kernel_launch(void* const* d_in, const int* in_sizes, int n_in,
                              void* d_out, int out_size)
{
    const float* tp    = (const float*)d_in[0];   // (F,3,3)
    const float* rot   = (const float*)d_in[1];   // (F,3,3)
    const float* verts = (const float*)d_in[2];   // (1,V,3)

    int V = in_sizes[2] / 3;
    int n = (int)(sqrt((double)V) + 0.5);
    int m = n - 1;

    dim3 block(256, 1, 1);
    dim3 grid((m + 255) / 256, m, 1);
    int nblocks = grid.x * grid.y;

    k_cell<<<grid, block>>>(tp, rot, verts, (float*)d_out, n, nblocks);
}